// round 15
// baseline (speedup 1.0000x reference)
#include <cuda_runtime.h>
#include <cstdint>
#include <math.h>

// Problem constants
#define O_NODES 10000
#define T_EDGES 50000
#define HH      512
#define NG      2048
#define HIST_SZ 131072

// ---------------- scratch (__device__ globals) --------------------------------
__device__ float g_predr[(size_t)T_EDGES * 128];
__device__ float g_ps  [(size_t)O_NODES * HH];         // obj @ W1[:, 0:128]^T
__device__ float g_po  [(size_t)O_NODES * HH];         // obj @ W1[:, 256:384]^T
__device__ float g_mid [(size_t)T_EDGES * HH];
__device__ float g_x32 [(size_t)(2 * T_EDGES) * HH];   // [new_s rows | new_o rows]
__device__ float g_hsA [(size_t)O_NODES * HH];         // h ping-pong buffer 0
__device__ float g_hsB [(size_t)O_NODES * HH];         // h ping-pong buffer 1
__device__ float g_cs  [(size_t)O_NODES * HH];         // full fp32 c state
__device__ float g_ac  [(size_t)O_NODES * 640];        // [pooled(512) | obj32(128)]
__device__ float g_obj32[(size_t)O_NODES * 128];
// tf32-rounded weights
__device__ float g_w1r  [512  * 384];
__device__ float g_w2r  [1152 * 512];
__device__ float g_whx  [2048 * 1024];            // [Whh_perm | Wih_perm] rows
__device__ float g_wcomb[128 * 640];              // [Wout_pool | Wout_prev@Wproj]
__device__ float g_bias [2048];                   // permuted bih+bhh
__device__ float g_bias2[128];                    // bout + bproj@Wout_prev^T
__device__ float g_h1[512];
__device__ float g_c1[512];
__device__ float g_ghh1[2048];                    // h1 @ Whh^T (permuted cols)
// sort scratch
__device__ int g_hist[HIST_SZ];
__device__ int g_cursor[HIST_SZ];
__device__ int g_cnt[HIST_SZ];
__device__ int g_order[O_NODES];
__device__ int g_pos[O_NODES];

// ---------------- helpers ------------------------------------------------------
__device__ __forceinline__ float roundtf(float x) {
    unsigned u;
    asm("cvt.rna.tf32.f32 %0, %1;" : "=r"(u) : "f"(x));
    return __uint_as_float(u);
}
__device__ __forceinline__ float sigm(float x) { return 1.f / (1.f + expf(-x)); }

__device__ __forceinline__ void mma_tf32(float* d, const unsigned* a, const unsigned* b) {
    asm volatile(
        "mma.sync.aligned.m16n8k8.row.col.f32.tf32.tf32.f32 "
        "{%0,%1,%2,%3}, {%4,%5,%6,%7}, {%8,%9}, {%0,%1,%2,%3};\n"
        : "+f"(d[0]), "+f"(d[1]), "+f"(d[2]), "+f"(d[3])
        : "r"(a[0]), "r"(a[1]), "r"(a[2]), "r"(a[3]), "r"(b[0]), "r"(b[1]));
}
__device__ __forceinline__ void cpa16(unsigned sdst, const float* gsrc, int src_bytes) {
    asm volatile("cp.async.cg.shared.global [%0], [%1], 16, %2;\n"
                 :: "r"(sdst), "l"(gsrc), "r"(src_bytes) : "memory");
}
__device__ __forceinline__ void cpa_commit() {
    asm volatile("cp.async.commit_group;\n" ::: "memory");
}
template<int N>
__device__ __forceinline__ void cpa_wait() {
    asm volatile("cp.async.wait_group %0;\n" :: "n"(N) : "memory");
}

#define PITCH   36
#define ASTG    (128 * PITCH)          // floats per A stage
#define TG_SMEM (4 * ASTG * 4)         // bytes: 2 stages x (A+B)

// ---------------- tf32 tensor-core GEMM ----------------------------------------
// C[M,N] = epi(A[M,K] @ B[N,K]^T). Inputs pre-rounded to tf32. B row stride Bld.
// Block 128x128, 4 warps x (64x64), BK=32 per stage, 2-stage cp.async.
// EPI: 0 exact(+bias) | 2 newt-split: relu; cols<512 -> round->X rows;
//      [512,640) -> fp32 C (new_p); >=640 -> round->X rows+T_EDGES
//      | 5 edge-mlp1: relu(acc + Ps[s]+Po[o] + bias) -> round -> C
template<int EPI, bool BIAS>
__global__ void __launch_bounds__(128, 2)
tgemm(const float* __restrict__ A, int lda,
      const float* __restrict__ B, int Bld, int K,
      const float* __restrict__ bias,
      float* __restrict__ C, int ldc,
      float* __restrict__ X, int M,
      const int* __restrict__ edges)
{
    const int m0 = blockIdx.y * 128;
    if (m0 >= M) return;
    const int n0 = blockIdx.x * 128;

    extern __shared__ float smem[];
    __shared__ int s_s[128], s_o[128];
    const unsigned sbase = (unsigned)__cvta_generic_to_shared(smem);

    const int tid  = threadIdx.x;
    const int warp = tid >> 5, lane = tid & 31;
    const int r = lane >> 2, c = lane & 3;
    const int wm = (warp & 1) * 64;
    const int wn = (warp >> 1) * 64;

    if (EPI == 5) {
        int row = m0 + tid;
        int s = 0, o = 0;
        if (row < M) { s = edges[2 * row]; o = edges[2 * row + 1]; }
        s_s[tid] = s;
        s_o[tid] = o;
        // ordered before epilogue reads by the mainloop's __syncthreads
    }

    float acc[4][8][4];
#pragma unroll
    for (int i = 0; i < 4; i++)
#pragma unroll
        for (int j = 0; j < 8; j++)
#pragma unroll
            for (int q = 0; q < 4; q++) acc[i][j][q] = 0.f;

    const int nk = K >> 5;

    auto load_stage = [&](int it, int stg) {
        int k0 = it << 5;
#pragma unroll
        for (int i = 0; i < 8; i++) {
            int q = tid + i * 128;
            int row = q >> 3, f4 = q & 7;
            unsigned soff = (unsigned)((stg * ASTG + row * PITCH + f4 * 4) * 4);
            const float* ga = A + (size_t)(m0 + row) * lda + k0 + f4 * 4;
            cpa16(sbase + soff, ga, ((m0 + row) < M) ? 16 : 0);
            const float* gb = B + (size_t)(n0 + row) * Bld + k0 + f4 * 4;
            cpa16(sbase + (unsigned)(2 * ASTG * 4) + soff, gb, 16);
        }
        cpa_commit();
    };

    load_stage(0, 0);

    for (int it = 0; it < nk; ++it) {
        if (it + 1 < nk) { load_stage(it + 1, (it + 1) & 1); cpa_wait<1>(); }
        else             { cpa_wait<0>(); }
        __syncthreads();

        const float* As = smem + (it & 1) * ASTG;
        const float* Bs = smem + 2 * ASTG + (it & 1) * ASTG;
#pragma unroll
        for (int kk = 0; kk < 32; kk += 8) {
            unsigned ua[4][4], ub[8][2];
#pragma unroll
            for (int mt = 0; mt < 4; mt++) {
                int mb = wm + mt * 16 + r;
                ua[mt][0] = __float_as_uint(As[(mb    ) * PITCH + kk + c    ]);
                ua[mt][1] = __float_as_uint(As[(mb + 8) * PITCH + kk + c    ]);
                ua[mt][2] = __float_as_uint(As[(mb    ) * PITCH + kk + c + 4]);
                ua[mt][3] = __float_as_uint(As[(mb + 8) * PITCH + kk + c + 4]);
            }
#pragma unroll
            for (int nf = 0; nf < 8; nf++) {
                int nb = wn + nf * 8 + r;
                ub[nf][0] = __float_as_uint(Bs[nb * PITCH + kk + c    ]);
                ub[nf][1] = __float_as_uint(Bs[nb * PITCH + kk + c + 4]);
            }
#pragma unroll
            for (int mt = 0; mt < 4; mt++)
#pragma unroll
                for (int nf = 0; nf < 8; nf++)
                    mma_tf32(acc[mt][nf], ua[mt], ub[nf]);
        }
        __syncthreads();
    }

    const int cc2 = c * 2;
#pragma unroll
    for (int mt = 0; mt < 4; mt++) {
        int row0 = m0 + wm + mt * 16 + r;
#pragma unroll
        for (int nf = 0; nf < 8; nf++) {
            int col = n0 + wn + nf * 8 + cc2;
            float bx = 0.f, by = 0.f;
            if (BIAS) { bx = bias[col]; by = bias[col + 1]; }
#pragma unroll
            for (int h = 0; h < 2; h++) {
                int row = row0 + h * 8;
                if (row >= M) continue;
                float vx = acc[mt][nf][h * 2 + 0] + bx;
                float vy = acc[mt][nf][h * 2 + 1] + by;
                if (EPI == 5) {
                    int rl = row - m0;
                    const float* ps = g_ps + (size_t)s_s[rl] * HH + col;
                    const float* po = g_po + (size_t)s_o[rl] * HH + col;
                    vx += ps[0] + po[0];
                    vy += ps[1] + po[1];
                    vx = fmaxf(vx, 0.f); vy = fmaxf(vy, 0.f);
                    *(float2*)(C + (size_t)row * ldc + col) =
                        make_float2(roundtf(vx), roundtf(vy));
                } else if (EPI == 2) {
                    vx = fmaxf(vx, 0.f); vy = fmaxf(vy, 0.f);
                    if (col < 512) {
                        *(float2*)(X + (size_t)row * HH + col) =
                            make_float2(roundtf(vx), roundtf(vy));
                    } else if (col < 640) {
                        *(float2*)(C + (size_t)row * 128 + (col - 512)) =
                            make_float2(vx, vy);
                    } else {
                        *(float2*)(X + (size_t)(row + T_EDGES) * HH + (col - 640)) =
                            make_float2(roundtf(vx), roundtf(vy));
                    }
                } else {
                    *(float2*)(C + (size_t)row * ldc + col) = make_float2(vx, vy);
                }
            }
        }
    }
}

// ---------------- fused LSTM step: gates = [h|x_gathered] @ [Whh|Wih]^T --------
template<bool T1>
__global__ void __launch_bounds__(128, 2)
lstm_step(const float* __restrict__ hin,
          int t, int L, const int* __restrict__ nbr,
          const int* __restrict__ mdev,
          float* __restrict__ hout)
{
    const int M = *mdev;
    const int m0 = blockIdx.y * 128;
    if (m0 >= M) return;
    const int n0 = blockIdx.x * 128;

    extern __shared__ float smem[];
    __shared__ int sidx[128];
    const unsigned sbase = (unsigned)__cvta_generic_to_shared(smem);

    const int tid  = threadIdx.x;
    const int warp = tid >> 5, lane = tid & 31;
    const int r = lane >> 2, c = lane & 3;
    const int wm = (warp & 1) * 64;
    const int wn = (warp >> 1) * 64;

    if (tid < 128) {
        int row = m0 + tid;
        int s = 0;
        if (row < M) s = nbr[(size_t)g_order[row] * L + t] - 1;  // active => >0
        sidx[tid] = s;
    }
    __syncthreads();

    const float* Bw = T1 ? (g_whx + 512) : g_whx;
    const int K = T1 ? 512 : 1024;
    const int nk = K >> 5;

    float acc[4][8][4];
#pragma unroll
    for (int i = 0; i < 4; i++)
#pragma unroll
        for (int j = 0; j < 8; j++)
#pragma unroll
            for (int q = 0; q < 4; q++) acc[i][j][q] = 0.f;

    auto load_stage = [&](int it, int stg) {
        int k0 = it << 5;
#pragma unroll
        for (int i = 0; i < 8; i++) {
            int q = tid + i * 128;
            int row = q >> 3, f4 = q & 7;
            unsigned soff = (unsigned)((stg * ASTG + row * PITCH + f4 * 4) * 4);
            const float* ga;
            if (T1)            ga = g_x32 + (size_t)sidx[row] * HH + k0 + f4 * 4;
            else if (k0 < 512) ga = hin + (size_t)(m0 + row) * HH + k0 + f4 * 4;
            else               ga = g_x32 + (size_t)sidx[row] * HH + (k0 - 512) + f4 * 4;
            cpa16(sbase + soff, ga, ((m0 + row) < M) ? 16 : 0);
            const float* gb = Bw + (size_t)(n0 + row) * 1024 + k0 + f4 * 4;
            cpa16(sbase + (unsigned)(2 * ASTG * 4) + soff, gb, 16);
        }
        cpa_commit();
    };

    load_stage(0, 0);

    for (int it = 0; it < nk; ++it) {
        if (it + 1 < nk) { load_stage(it + 1, (it + 1) & 1); cpa_wait<1>(); }
        else             { cpa_wait<0>(); }
        __syncthreads();

        const float* As = smem + (it & 1) * ASTG;
        const float* Bs = smem + 2 * ASTG + (it & 1) * ASTG;
#pragma unroll
        for (int kk = 0; kk < 32; kk += 8) {
            unsigned ua[4][4], ub[8][2];
#pragma unroll
            for (int mt = 0; mt < 4; mt++) {
                int mb = wm + mt * 16 + r;
                ua[mt][0] = __float_as_uint(As[(mb    ) * PITCH + kk + c    ]);
                ua[mt][1] = __float_as_uint(As[(mb + 8) * PITCH + kk + c    ]);
                ua[mt][2] = __float_as_uint(As[(mb    ) * PITCH + kk + c + 4]);
                ua[mt][3] = __float_as_uint(As[(mb + 8) * PITCH + kk + c + 4]);
            }
#pragma unroll
            for (int nf = 0; nf < 8; nf++) {
                int nb = wn + nf * 8 + r;
                ub[nf][0] = __float_as_uint(Bs[nb * PITCH + kk + c    ]);
                ub[nf][1] = __float_as_uint(Bs[nb * PITCH + kk + c + 4]);
            }
#pragma unroll
            for (int mt = 0; mt < 4; mt++)
#pragma unroll
                for (int nf = 0; nf < 8; nf++)
                    mma_tf32(acc[mt][nf], ua[mt], ub[nf]);
        }
        __syncthreads();
    }

    // stage 128x128 gate tile in smem, then pointwise
    float* gbuf = smem;   // 128 x 132 floats = 67584 <= 73728
    const int cc2 = c * 2;
#pragma unroll
    for (int mt = 0; mt < 4; mt++) {
        int lr0 = wm + mt * 16 + r;
#pragma unroll
        for (int nf = 0; nf < 8; nf++) {
            int col = wn + nf * 8 + cc2;
            gbuf[lr0 * 132 + col]           = acc[mt][nf][0];
            gbuf[lr0 * 132 + col + 1]       = acc[mt][nf][1];
            gbuf[(lr0 + 8) * 132 + col]     = acc[mt][nf][2];
            gbuf[(lr0 + 8) * 132 + col + 1] = acc[mt][nf][3];
        }
    }
    __syncthreads();
    const int jj0 = (tid & 3) * 8;
#pragma unroll
    for (int pass = 0; pass < 4; pass++) {
        int rl = pass * 32 + (tid >> 2);
        int row = m0 + rl;
        if (row < M) {
#pragma unroll
            for (int u = 0; u < 8; u++) {
                int jj = jj0 + u;
                float gi = gbuf[rl * 132 + jj]      + g_bias[n0 + jj];
                float gf = gbuf[rl * 132 + 32 + jj] + g_bias[n0 + 32 + jj];
                float gg = gbuf[rl * 132 + 64 + jj] + g_bias[n0 + 64 + jj];
                float go = gbuf[rl * 132 + 96 + jj] + g_bias[n0 + 96 + jj];
                if (T1) {
                    gi += g_ghh1[n0 + jj];
                    gf += g_ghh1[n0 + 32 + jj];
                    gg += g_ghh1[n0 + 64 + jj];
                    go += g_ghh1[n0 + 96 + jj];
                }
                int j = (n0 >> 2) + jj;    // global hidden index
                float cc = g_cs[(size_t)row * HH + j];
                float c2 = sigm(gf) * cc + sigm(gi) * tanhf(gg);
                float h2 = sigm(go) * tanhf(c2);
                g_cs[(size_t)row * HH + j] = c2;
                hout[(size_t)row * HH + j] = roundtf(h2);
            }
        }
    }
}

// ---------------- prep / pointwise kernels -------------------------------------
#define PRE_W1    0
#define PRE_W2    (PRE_W1 + 512 * 384)
#define PRE_WIH   (PRE_W2 + 1152 * 512)
#define PRE_WHH   (PRE_WIH + 2048 * 512)
#define PRE_WOUTP (PRE_WHH + 2048 * 512)
#define PRE_PRED  (PRE_WOUTP + 128 * 512)
#define PRE_OBJ   (PRE_PRED + T_EDGES * 128)
#define PRE_BIAS  (PRE_OBJ + O_NODES * 128)
#define PRE_TOTAL (PRE_BIAS + 2048)

__global__ void k_prep(const float* __restrict__ W1, const float* __restrict__ W2,
                       const float* __restrict__ Wih, const float* __restrict__ Whh,
                       const float* __restrict__ Wout,
                       const float* __restrict__ pred, const float* __restrict__ obj,
                       const float* __restrict__ bih, const float* __restrict__ bhh)
{
    int i = blockIdx.x * blockDim.x + threadIdx.x;
    if (i >= PRE_TOTAL) return;
    if (i < PRE_W2) {
        g_w1r[i] = roundtf(W1[i]);
    } else if (i < PRE_WIH) {
        int q = i - PRE_W2;  g_w2r[q] = roundtf(W2[q]);
    } else if (i < PRE_WOUTP) {
        int q = (i < PRE_WHH) ? (i - PRE_WIH) : (i - PRE_WHH);
        const float* W = (i < PRE_WHH) ? Wih : Whh;
        int half = (i < PRE_WHH) ? 512 : 0;    // Wih -> cols [512,1024), Whh -> [0,512)
        int p = q >> 9, k = q & 511;
        int g = (p >> 5) & 3, tg = p >> 7, jj = p & 31;
        int orig = g * 512 + tg * 32 + jj;
        g_whx[(size_t)p * 1024 + half + k] = roundtf(W[(size_t)orig * 512 + k]);
    } else if (i < PRE_PRED) {
        int q = i - PRE_WOUTP;                 // Wout[:, :512] -> g_wcomb cols [0,512)
        int j = q >> 9, k = q & 511;
        g_wcomb[(size_t)j * 640 + k] = roundtf(Wout[(size_t)j * 1024 + k]);
    } else if (i < PRE_OBJ) {
        int q = i - PRE_PRED;  g_predr[q] = roundtf(pred[q]);
    } else if (i < PRE_BIAS) {
        int q = i - PRE_OBJ;
        float v = roundtf(obj[q]);
        g_obj32[q] = v;
        g_ac[(size_t)(q >> 7) * 640 + 512 + (q & 127)] = v;
    } else {
        int p = i - PRE_BIAS;
        int g = (p >> 5) & 3, tg = p >> 7, jj = p & 31;
        int orig = g * 512 + tg * 32 + jj;
        g_bias[p] = bih[orig] + bhh[orig];
    }
}

// Wcomb[j][k] = sum_m Wout[j][512+m] * Wproj[m][k]  -> g_wcomb cols [512,640)
__global__ void k_wcomb(const float* __restrict__ Wout, const float* __restrict__ Wproj)
{
    int j = blockIdx.x, k = threadIdx.x;
    float s = 0.f;
    for (int m = 0; m < 512; ++m)
        s = fmaf(Wout[(size_t)j * 1024 + 512 + m], Wproj[(size_t)m * 128 + k], s);
    g_wcomb[(size_t)j * 640 + 512 + k] = roundtf(s);
}

// bias2[j] = bout[j] + sum_m bproj[m] * Wout[j][512+m]
__global__ void k_bias2(const float* __restrict__ Wout, const float* __restrict__ bproj,
                        const float* __restrict__ bout)
{
    int j = threadIdx.x;
    float s = bout[j];
    for (int m = 0; m < 512; ++m)
        s = fmaf(bproj[m], Wout[(size_t)j * 1024 + 512 + m], s);
    g_bias2[j] = s;
}

__global__ void k_zero_hist()
{
    int i = blockIdx.x * blockDim.x + threadIdx.x;
    if (i < HIST_SZ) g_hist[i] = 0;
}
__global__ void k_hist(const int* __restrict__ lengths)
{
    int n = blockIdx.x * blockDim.x + threadIdx.x;
    if (n < O_NODES) atomicAdd(&g_hist[lengths[n]], 1);
}
__global__ void k_scan(int L)
{
    int run = 0;
    for (int len = L; len >= 0; --len) {
        g_cursor[len] = run;
        g_cnt[len]    = run;
        run += g_hist[len];
    }
}
__global__ void k_scatter(const int* __restrict__ lengths)
{
    int n = blockIdx.x * blockDim.x + threadIdx.x;
    if (n >= O_NODES) return;
    int pos = atomicAdd(&g_cursor[lengths[n]], 1);
    g_order[pos] = n;
    g_pos[n] = pos;
}

// step 0: x=0, h=0 -> gates = biases only; identical for all nodes
__global__ void k_step0a()
{
    int j = threadIdx.x;
    int tg = j >> 5, jj = j & 31;
    int base = tg * 128 + jj;
    float gi = g_bias[base];
    float gf = g_bias[base + 32];
    float gg = g_bias[base + 64];
    float go = g_bias[base + 96];
    float c1 = sigm(gi) * tanhf(gg);          // c0 = 0
    float h1 = sigm(go) * tanhf(c1);
    g_c1[j] = c1;
    g_h1[j] = roundtf(h1);
}
__global__ void k_step0b()
{
    int i = blockIdx.x * blockDim.x + threadIdx.x;
    if (i >= O_NODES * HH) return;
    g_cs[i]  = g_c1[i & 511];
    g_hsB[i] = g_h1[i & 511];
}

// ghh1[p] = sum_k h1[k] * Whh_perm[p][k]
__global__ void k_ghh1()
{
    int p = blockIdx.x * blockDim.x + threadIdx.x;
    if (p >= 2048) return;
    const float* w = g_whx + (size_t)p * 1024;
    float s = 0.f;
    for (int k = 0; k < 512; ++k) s = fmaf(g_h1[k], w[k], s);
    g_ghh1[p] = s;
}

// pooled half of ac: ac[n][0..127 f4] = hbuf[lengths[n]&1][pos[n]]
__global__ void k_build_ac(const int* __restrict__ lengths)
{
    int i = blockIdx.x * blockDim.x + threadIdx.x;
    if (i >= O_NODES * 128) return;
    int n = i >> 7, q = i & 127;
    const float* hb = (lengths[n] & 1) ? g_hsB : g_hsA;
    ((float4*)(g_ac + (size_t)n * 640))[q] =
        ((const float4*)hb)[(size_t)g_pos[n] * 128 + q];
}

// ---------------- launcher -----------------------------------------------------
extern "C" void kernel_launch(void* const* d_in, const int* in_sizes, int n_in,
                              void* d_out, int out_size)
{
    const float* obj    = (const float*)d_in[0];
    const float* pred   = (const float*)d_in[1];
    const int*   edges  = (const int*)  d_in[2];
    const int*   nbr    = (const int*)  d_in[3];
    const int*   lengths= (const int*)  d_in[4];
    const float* W1     = (const float*)d_in[5];
    const float* b1     = (const float*)d_in[6];
    const float* W2     = (const float*)d_in[7];
    const float* b2     = (const float*)d_in[8];
    const float* Wih    = (const float*)d_in[9];
    const float* Whh    = (const float*)d_in[10];
    const float* bih    = (const float*)d_in[11];
    const float* bhh    = (const float*)d_in[12];
    const float* Wproj  = (const float*)d_in[13];
    const float* bproj  = (const float*)d_in[14];
    const float* Wout   = (const float*)d_in[15];
    const float* bout   = (const float*)d_in[16];
    float* out = (float*)d_out;

    const int L = in_sizes[3] / O_NODES;

    float *p_predr, *p_ps, *p_po, *p_mid, *p_x32, *p_hsA, *p_hsB, *p_ac, *p_obj32;
    float *p_w1, *p_w2, *p_wcomb, *p_bias2;
    int *p_cnt;
    cudaGetSymbolAddress((void**)&p_predr, g_predr);
    cudaGetSymbolAddress((void**)&p_ps,    g_ps);
    cudaGetSymbolAddress((void**)&p_po,    g_po);
    cudaGetSymbolAddress((void**)&p_mid,   g_mid);
    cudaGetSymbolAddress((void**)&p_x32,   g_x32);
    cudaGetSymbolAddress((void**)&p_hsA,   g_hsA);
    cudaGetSymbolAddress((void**)&p_hsB,   g_hsB);
    cudaGetSymbolAddress((void**)&p_ac,    g_ac);
    cudaGetSymbolAddress((void**)&p_obj32, g_obj32);
    cudaGetSymbolAddress((void**)&p_w1,    g_w1r);
    cudaGetSymbolAddress((void**)&p_w2,    g_w2r);
    cudaGetSymbolAddress((void**)&p_wcomb, g_wcomb);
    cudaGetSymbolAddress((void**)&p_bias2, g_bias2);
    cudaGetSymbolAddress((void**)&p_cnt,   g_cnt);

    cudaFuncSetAttribute(tgemm<0, false>, cudaFuncAttributeMaxDynamicSharedMemorySize, TG_SMEM);
    cudaFuncSetAttribute(tgemm<0, true >, cudaFuncAttributeMaxDynamicSharedMemorySize, TG_SMEM);
    cudaFuncSetAttribute(tgemm<2, true >, cudaFuncAttributeMaxDynamicSharedMemorySize, TG_SMEM);
    cudaFuncSetAttribute(tgemm<5, true >, cudaFuncAttributeMaxDynamicSharedMemorySize, TG_SMEM);
    cudaFuncSetAttribute(lstm_step<true >, cudaFuncAttributeMaxDynamicSharedMemorySize, TG_SMEM);
    cudaFuncSetAttribute(lstm_step<false>, cudaFuncAttributeMaxDynamicSharedMemorySize, TG_SMEM);

    const int MT_E = (T_EDGES + 127) / 128;        // 391
    const int MT_O = (O_NODES + 127) / 128;        // 79

    // prep (weight rounding/permutation, Wout_pool, pred/obj round, bias)
    k_prep<<<(PRE_TOTAL + 255) / 256, 256>>>(W1, W2, Wih, Whh, Wout, pred, obj, bih, bhh);
    k_wcomb<<<128, 128>>>(Wout, Wproj);
    k_bias2<<<1, 128>>>(Wout, bproj, bout);

    // node sort by length (descending)
    k_zero_hist<<<HIST_SZ / 256, 256>>>();
    k_hist<<<(O_NODES + 255) / 256, 256>>>(lengths);
    k_scan<<<1, 1>>>(L);
    k_scatter<<<(O_NODES + 255) / 256, 256>>>(lengths);

    // node projections through W1 slices: Ps = obj@W1[:,0:128]^T, Po = obj@W1[:,256:384]^T
    tgemm<0, false><<<dim3(4, MT_O), 128, TG_SMEM>>>(p_obj32, 128, p_w1,       384, 128,
        nullptr, p_ps, 512, nullptr, O_NODES, nullptr);
    tgemm<0, false><<<dim3(4, MT_O), 128, TG_SMEM>>>(p_obj32, 128, p_w1 + 256, 384, 128,
        nullptr, p_po, 512, nullptr, O_NODES, nullptr);

    // edge MLP1: mid = relu(pred@W1p^T + Ps[s] + Po[o] + b1), rounded
    tgemm<5, true ><<<dim3(4, MT_E), 128, TG_SMEM>>>(p_predr, 128, p_w1 + 128, 384, 128,
        b1, p_mid, 512, nullptr, T_EDGES, edges);
    // edge MLP2: split-write new_s/new_o (rounded) to g_x32, new_p to out
    tgemm<2, true ><<<dim3(9, MT_E), 128, TG_SMEM>>>(p_mid, 512, p_w2, 512, 512,
        b2, out + (size_t)O_NODES * 128, 128, p_x32, T_EDGES, nullptr);

    // LSTM: step 0 closed form (buffer B); step 1 = x-only GEMM + ghh1 broadcast
    // (buffer A); steps t=2..L-1 fused [h|x] GEMM + pointwise, ping-pong.
    k_step0a<<<1, 512>>>();
    k_step0b<<<(O_NODES * HH + 255) / 256, 256>>>();
    k_ghh1<<<8, 256>>>();
    lstm_step<true ><<<dim3(16, MT_O), 128, TG_SMEM>>>(p_hsB, 1, L, nbr, p_cnt + 1, p_hsA);
    for (int t = 2; t < L; ++t) {
        float* hin  = (t & 1) ? p_hsB : p_hsA;
        float* hout = (t & 1) ? p_hsA : p_hsB;
        lstm_step<false><<<dim3(16, MT_O), 128, TG_SMEM>>>(hin, t, L, nbr, p_cnt + t, hout);
    }

    // new_obj = [pooled | obj] @ [Wout_pool | Wcomb]^T + bias2 (exact epilogue)
    k_build_ac<<<(O_NODES * 128 + 255) / 256, 256>>>(lengths);
    tgemm<0, true ><<<dim3(1, MT_O), 128, TG_SMEM>>>(p_ac, 640, p_wcomb, 640, 640,
        p_bias2, out, 128, nullptr, O_NODES, nullptr);
}

// round 16
// speedup vs baseline: 1.0012x; 1.0012x over previous
#include <cuda_runtime.h>
#include <cstdint>
#include <math.h>

// Problem constants
#define O_NODES 10000
#define T_EDGES 50000
#define HH      512
#define NG      2048
#define HIST_SZ 131072

// ---------------- scratch (__device__ globals) --------------------------------
__device__ float g_cur [(size_t)T_EDGES * 384];
__device__ float g_mid [(size_t)T_EDGES * HH];
__device__ float g_x32 [(size_t)(2 * T_EDGES) * HH];   // [new_s rows | new_o rows]
__device__ float g_hsA [(size_t)O_NODES * HH];         // h ping-pong buffer 0
__device__ float g_hsB [(size_t)O_NODES * HH];         // h ping-pong buffer 1
__device__ float g_cs  [(size_t)O_NODES * HH];         // full fp32 c state
__device__ float g_pc  [(size_t)O_NODES * 1024];       // [pooled | prev]
__device__ float g_obj32[(size_t)O_NODES * 128];
// tf32-rounded weights
__device__ float g_w1r   [512  * 384];
__device__ float g_w2r   [1152 * 512];
__device__ float g_whx   [2048 * 1024];           // [Whh_perm | Wih_perm] rows
__device__ float g_wprojr[512  * 128];
__device__ float g_woutr [128  * 1024];
__device__ float g_bias  [2048];                  // permuted bih+bhh
__device__ float g_h1[512];
__device__ float g_c1[512];
__device__ float g_ghh1[2048];                    // h1 @ Whh^T (permuted cols)
// sort scratch
__device__ int g_hist[HIST_SZ];
__device__ int g_cursor[HIST_SZ];
__device__ int g_cnt[HIST_SZ];
__device__ int g_order[O_NODES];
__device__ int g_pos[O_NODES];

// ---------------- helpers ------------------------------------------------------
__device__ __forceinline__ float roundtf(float x) {
    unsigned u;
    asm("cvt.rna.tf32.f32 %0, %1;" : "=r"(u) : "f"(x));
    return __uint_as_float(u);
}
__device__ __forceinline__ float sigm(float x) { return 1.f / (1.f + expf(-x)); }

__device__ __forceinline__ void mma_tf32(float* d, const unsigned* a, const unsigned* b) {
    asm volatile(
        "mma.sync.aligned.m16n8k8.row.col.f32.tf32.tf32.f32 "
        "{%0,%1,%2,%3}, {%4,%5,%6,%7}, {%8,%9}, {%0,%1,%2,%3};\n"
        : "+f"(d[0]), "+f"(d[1]), "+f"(d[2]), "+f"(d[3])
        : "r"(a[0]), "r"(a[1]), "r"(a[2]), "r"(a[3]), "r"(b[0]), "r"(b[1]));
}
__device__ __forceinline__ void cpa16(unsigned sdst, const float* gsrc, int src_bytes) {
    asm volatile("cp.async.cg.shared.global [%0], [%1], 16, %2;\n"
                 :: "r"(sdst), "l"(gsrc), "r"(src_bytes) : "memory");
}
__device__ __forceinline__ void cpa_commit() {
    asm volatile("cp.async.commit_group;\n" ::: "memory");
}
template<int N>
__device__ __forceinline__ void cpa_wait() {
    asm volatile("cp.async.wait_group %0;\n" :: "n"(N) : "memory");
}

#define PITCH   36
#define ASTG    (128 * PITCH)          // floats per stage array (A or B)
#define TG_SMEM (6 * ASTG * 4)         // bytes: 3 stages x (A+B) = 110592

// ---------------- tf32 tensor-core GEMM (3-stage, single sync/iter) ------------
// C[M,N] = epi(A[M,K] @ B[N,K]^T). Inputs pre-rounded to tf32.
// Block 128x128, 4 warps x (64x64), BK=32 per stage.
// EPI: 0 exact(+bias) | 1 relu+round(+bias) | 2 newt-split: relu; cols<512 ->
//      round->X rows; [512,640) -> fp32 C (new_p); >=640 -> round->X rows+T_EDGES
//      | 3 round(+bias)
template<int EPI, bool BIAS>
__global__ void __launch_bounds__(128, 2)
tgemm(const float* __restrict__ A, int lda,
      const float* __restrict__ B, int K,
      const float* __restrict__ bias,
      float* __restrict__ C, int ldc,
      float* __restrict__ X, int M)
{
    const int m0 = blockIdx.y * 128;
    if (m0 >= M) return;
    const int n0 = blockIdx.x * 128;

    extern __shared__ float smem[];
    const unsigned sbase = (unsigned)__cvta_generic_to_shared(smem);

    const int tid  = threadIdx.x;
    const int warp = tid >> 5, lane = tid & 31;
    const int r = lane >> 2, c = lane & 3;
    const int wm = (warp & 1) * 64;
    const int wn = (warp >> 1) * 64;

    float acc[4][8][4];
#pragma unroll
    for (int i = 0; i < 4; i++)
#pragma unroll
        for (int j = 0; j < 8; j++)
#pragma unroll
            for (int q = 0; q < 4; q++) acc[i][j][q] = 0.f;

    const int nk = K >> 5;

    auto load_stage = [&](int it, int stg) {
        int k0 = it << 5;
#pragma unroll
        for (int i = 0; i < 8; i++) {
            int q = tid + i * 128;
            int row = q >> 3, f4 = q & 7;
            unsigned soff = (unsigned)((stg * ASTG + row * PITCH + f4 * 4) * 4);
            const float* ga = A + (size_t)(m0 + row) * lda + k0 + f4 * 4;
            cpa16(sbase + soff, ga, ((m0 + row) < M) ? 16 : 0);
            const float* gb = B + (size_t)(n0 + row) * K + k0 + f4 * 4;
            cpa16(sbase + (unsigned)(3 * ASTG * 4) + soff, gb, 16);
        }
        cpa_commit();
    };

    load_stage(0, 0);
    if (nk > 1) load_stage(1, 1);

    for (int it = 0; it < nk; ++it) {
        if (it + 1 < nk) cpa_wait<1>(); else cpa_wait<0>();
        __syncthreads();
        if (it + 2 < nk) load_stage(it + 2, (it + 2) % 3);  // stage (it-1)%3: drained

        const float* As = smem + (it % 3) * ASTG;
        const float* Bs = smem + 3 * ASTG + (it % 3) * ASTG;
#pragma unroll
        for (int kk = 0; kk < 32; kk += 8) {
            unsigned ua[4][4], ub[8][2];
#pragma unroll
            for (int mt = 0; mt < 4; mt++) {
                int mb = wm + mt * 16 + r;
                ua[mt][0] = __float_as_uint(As[(mb    ) * PITCH + kk + c    ]);
                ua[mt][1] = __float_as_uint(As[(mb + 8) * PITCH + kk + c    ]);
                ua[mt][2] = __float_as_uint(As[(mb    ) * PITCH + kk + c + 4]);
                ua[mt][3] = __float_as_uint(As[(mb + 8) * PITCH + kk + c + 4]);
            }
#pragma unroll
            for (int nf = 0; nf < 8; nf++) {
                int nb = wn + nf * 8 + r;
                ub[nf][0] = __float_as_uint(Bs[nb * PITCH + kk + c    ]);
                ub[nf][1] = __float_as_uint(Bs[nb * PITCH + kk + c + 4]);
            }
#pragma unroll
            for (int mt = 0; mt < 4; mt++)
#pragma unroll
                for (int nf = 0; nf < 8; nf++)
                    mma_tf32(acc[mt][nf], ua[mt], ub[nf]);
        }
    }

    const int cc2 = c * 2;
#pragma unroll
    for (int mt = 0; mt < 4; mt++) {
        int row0 = m0 + wm + mt * 16 + r;
#pragma unroll
        for (int nf = 0; nf < 8; nf++) {
            int col = n0 + wn + nf * 8 + cc2;
            float bx = 0.f, by = 0.f;
            if (BIAS) { bx = bias[col]; by = bias[col + 1]; }
#pragma unroll
            for (int h = 0; h < 2; h++) {
                int row = row0 + h * 8;
                if (row >= M) continue;
                float vx = acc[mt][nf][h * 2 + 0] + bx;
                float vy = acc[mt][nf][h * 2 + 1] + by;
                if (EPI == 1 || EPI == 2) { vx = fmaxf(vx, 0.f); vy = fmaxf(vy, 0.f); }
                if (EPI == 1 || EPI == 3) { vx = roundtf(vx); vy = roundtf(vy); }
                if (EPI == 2) {
                    if (col < 512) {
                        *(float2*)(X + (size_t)row * HH + col) =
                            make_float2(roundtf(vx), roundtf(vy));
                    } else if (col < 640) {
                        *(float2*)(C + (size_t)row * 128 + (col - 512)) =
                            make_float2(vx, vy);
                    } else {
                        *(float2*)(X + (size_t)(row + T_EDGES) * HH + (col - 640)) =
                            make_float2(roundtf(vx), roundtf(vy));
                    }
                } else {
                    *(float2*)(C + (size_t)row * ldc + col) = make_float2(vx, vy);
                }
            }
        }
    }
}

// ---------------- fused LSTM step: gates = [h|x_gathered] @ [Whh|Wih]^T --------
// T1: step 1 — x-only GEMM (K=512, B=Wih half), ghh1 broadcast added in epilogue.
// else: K=1024; stages <512 read h from hin, >=512 read x row sidx[row].
template<bool T1>
__global__ void __launch_bounds__(128, 2)
lstm_step(const float* __restrict__ hin,
          int t, int L, const int* __restrict__ nbr,
          const int* __restrict__ mdev,
          float* __restrict__ hout)
{
    const int M = *mdev;
    const int m0 = blockIdx.y * 128;
    if (m0 >= M) return;
    const int n0 = blockIdx.x * 128;

    extern __shared__ float smem[];
    __shared__ int sidx[128];
    const unsigned sbase = (unsigned)__cvta_generic_to_shared(smem);

    const int tid  = threadIdx.x;
    const int warp = tid >> 5, lane = tid & 31;
    const int r = lane >> 2, c = lane & 3;
    const int wm = (warp & 1) * 64;
    const int wn = (warp >> 1) * 64;

    {
        int row = m0 + tid;
        int s = 0;
        if (row < M) s = nbr[(size_t)g_order[row] * L + t] - 1;  // active => >0
        sidx[tid] = s;
    }
    __syncthreads();

    const float* Bw = T1 ? (g_whx + 512) : g_whx;
    const int K = T1 ? 512 : 1024;
    const int nk = K >> 5;

    float acc[4][8][4];
#pragma unroll
    for (int i = 0; i < 4; i++)
#pragma unroll
        for (int j = 0; j < 8; j++)
#pragma unroll
            for (int q = 0; q < 4; q++) acc[i][j][q] = 0.f;

    auto load_stage = [&](int it, int stg) {
        int k0 = it << 5;
#pragma unroll
        for (int i = 0; i < 8; i++) {
            int q = tid + i * 128;
            int row = q >> 3, f4 = q & 7;
            unsigned soff = (unsigned)((stg * ASTG + row * PITCH + f4 * 4) * 4);
            const float* ga;
            if (T1)            ga = g_x32 + (size_t)sidx[row] * HH + k0 + f4 * 4;
            else if (k0 < 512) ga = hin + (size_t)(m0 + row) * HH + k0 + f4 * 4;
            else               ga = g_x32 + (size_t)sidx[row] * HH + (k0 - 512) + f4 * 4;
            cpa16(sbase + soff, ga, ((m0 + row) < M) ? 16 : 0);
            const float* gb = Bw + (size_t)(n0 + row) * 1024 + k0 + f4 * 4;
            cpa16(sbase + (unsigned)(3 * ASTG * 4) + soff, gb, 16);
        }
        cpa_commit();
    };

    load_stage(0, 0);
    if (nk > 1) load_stage(1, 1);

    for (int it = 0; it < nk; ++it) {
        if (it + 1 < nk) cpa_wait<1>(); else cpa_wait<0>();
        __syncthreads();
        if (it + 2 < nk) load_stage(it + 2, (it + 2) % 3);

        const float* As = smem + (it % 3) * ASTG;
        const float* Bs = smem + 3 * ASTG + (it % 3) * ASTG;
#pragma unroll
        for (int kk = 0; kk < 32; kk += 8) {
            unsigned ua[4][4], ub[8][2];
#pragma unroll
            for (int mt = 0; mt < 4; mt++) {
                int mb = wm + mt * 16 + r;
                ua[mt][0] = __float_as_uint(As[(mb    ) * PITCH + kk + c    ]);
                ua[mt][1] = __float_as_uint(As[(mb + 8) * PITCH + kk + c    ]);
                ua[mt][2] = __float_as_uint(As[(mb    ) * PITCH + kk + c + 4]);
                ua[mt][3] = __float_as_uint(As[(mb + 8) * PITCH + kk + c + 4]);
            }
#pragma unroll
            for (int nf = 0; nf < 8; nf++) {
                int nb = wn + nf * 8 + r;
                ub[nf][0] = __float_as_uint(Bs[nb * PITCH + kk + c    ]);
                ub[nf][1] = __float_as_uint(Bs[nb * PITCH + kk + c + 4]);
            }
#pragma unroll
            for (int mt = 0; mt < 4; mt++)
#pragma unroll
                for (int nf = 0; nf < 8; nf++)
                    mma_tf32(acc[mt][nf], ua[mt], ub[nf]);
        }
    }
    __syncthreads();   // all warps done reading smem before gbuf overlay

    // stage 128x128 gate tile in smem, then pointwise
    float* gbuf = smem;   // 128 x 132 floats = 67584 <= 110592
    const int cc2 = c * 2;
#pragma unroll
    for (int mt = 0; mt < 4; mt++) {
        int lr0 = wm + mt * 16 + r;
#pragma unroll
        for (int nf = 0; nf < 8; nf++) {
            int col = wn + nf * 8 + cc2;
            gbuf[lr0 * 132 + col]           = acc[mt][nf][0];
            gbuf[lr0 * 132 + col + 1]       = acc[mt][nf][1];
            gbuf[(lr0 + 8) * 132 + col]     = acc[mt][nf][2];
            gbuf[(lr0 + 8) * 132 + col + 1] = acc[mt][nf][3];
        }
    }
    __syncthreads();
    const int jj0 = (tid & 3) * 8;
#pragma unroll
    for (int pass = 0; pass < 4; pass++) {
        int rl = pass * 32 + (tid >> 2);
        int row = m0 + rl;
        if (row < M) {
#pragma unroll
            for (int u = 0; u < 8; u++) {
                int jj = jj0 + u;
                float gi = gbuf[rl * 132 + jj]      + g_bias[n0 + jj];
                float gf = gbuf[rl * 132 + 32 + jj] + g_bias[n0 + 32 + jj];
                float gg = gbuf[rl * 132 + 64 + jj] + g_bias[n0 + 64 + jj];
                float go = gbuf[rl * 132 + 96 + jj] + g_bias[n0 + 96 + jj];
                if (T1) {
                    gi += g_ghh1[n0 + jj];
                    gf += g_ghh1[n0 + 32 + jj];
                    gg += g_ghh1[n0 + 64 + jj];
                    go += g_ghh1[n0 + 96 + jj];
                }
                int j = (n0 >> 2) + jj;    // global hidden index
                float cc = g_cs[(size_t)row * HH + j];
                float c2 = sigm(gf) * cc + sigm(gi) * tanhf(gg);
                float h2 = sigm(go) * tanhf(c2);
                g_cs[(size_t)row * HH + j] = c2;
                hout[(size_t)row * HH + j] = roundtf(h2);
            }
        }
    }
}

// ---------------- prep / pointwise kernels -------------------------------------
#define PRE_W1    0
#define PRE_W2    (PRE_W1 + 512 * 384)
#define PRE_WIH   (PRE_W2 + 1152 * 512)
#define PRE_WHH   (PRE_WIH + 2048 * 512)
#define PRE_WPROJ (PRE_WHH + 2048 * 512)
#define PRE_WOUT  (PRE_WPROJ + 512 * 128)
#define PRE_OBJ   (PRE_WOUT + 128 * 1024)
#define PRE_BIAS  (PRE_OBJ + O_NODES * 128)
#define PRE_HIST  (PRE_BIAS + 2048)
#define PRE_TOTAL (PRE_HIST + HIST_SZ)

__global__ void k_prep(const float* __restrict__ W1, const float* __restrict__ W2,
                       const float* __restrict__ Wih, const float* __restrict__ Whh,
                       const float* __restrict__ Wproj, const float* __restrict__ Wout,
                       const float* __restrict__ obj,
                       const float* __restrict__ bih, const float* __restrict__ bhh)
{
    int i = blockIdx.x * blockDim.x + threadIdx.x;
    if (i >= PRE_TOTAL) return;
    if (i < PRE_W2) {
        g_w1r[i] = roundtf(W1[i]);
    } else if (i < PRE_WIH) {
        int q = i - PRE_W2;  g_w2r[q] = roundtf(W2[q]);
    } else if (i < PRE_WPROJ) {
        int q = (i < PRE_WHH) ? (i - PRE_WIH) : (i - PRE_WHH);
        const float* W = (i < PRE_WHH) ? Wih : Whh;
        int half = (i < PRE_WHH) ? 512 : 0;    // Wih -> cols [512,1024), Whh -> [0,512)
        int p = q >> 9, k = q & 511;
        int g = (p >> 5) & 3, tg = p >> 7, jj = p & 31;
        int orig = g * 512 + tg * 32 + jj;
        g_whx[(size_t)p * 1024 + half + k] = roundtf(W[(size_t)orig * 512 + k]);
    } else if (i < PRE_WOUT) {
        int q = i - PRE_WPROJ;  g_wprojr[q] = roundtf(Wproj[q]);
    } else if (i < PRE_OBJ) {
        int q = i - PRE_WOUT;  g_woutr[q] = roundtf(Wout[q]);
    } else if (i < PRE_BIAS) {
        int q = i - PRE_OBJ;  g_obj32[q] = roundtf(obj[q]);
    } else if (i < PRE_HIST) {
        int p = i - PRE_BIAS;
        int g = (p >> 5) & 3, tg = p >> 7, jj = p & 31;
        int orig = g * 512 + tg * 32 + jj;
        g_bias[p] = bih[orig] + bhh[orig];
    } else {
        g_hist[i - PRE_HIST] = 0;
    }
}

__global__ void k_hist(const int* __restrict__ lengths)
{
    int n = blockIdx.x * blockDim.x + threadIdx.x;
    if (n < O_NODES) atomicAdd(&g_hist[lengths[n]], 1);
}
__global__ void k_scan(int L)
{
    int run = 0;
    for (int len = L; len >= 0; --len) {
        g_cursor[len] = run;
        g_cnt[len]    = run;
        run += g_hist[len];
    }
}
__global__ void k_scatter(const int* __restrict__ lengths)
{
    int n = blockIdx.x * blockDim.x + threadIdx.x;
    if (n >= O_NODES) return;
    int pos = atomicAdd(&g_cursor[lengths[n]], 1);
    g_order[pos] = n;
    g_pos[n] = pos;
}

__global__ void k_build_cur(const float* __restrict__ obj,
                            const float* __restrict__ pred,
                            const int* __restrict__ edges)
{
    int i = blockIdx.x * blockDim.x + threadIdx.x;
    if (i >= T_EDGES * 384) return;
    int e = i / 384, q = i - e * 384;
    float v;
    if (q < 128)       v = obj[(size_t)edges[2 * e] * 128 + q];
    else if (q < 256)  v = pred[(size_t)e * 128 + (q - 128)];
    else               v = obj[(size_t)edges[2 * e + 1] * 128 + (q - 256)];
    g_cur[(size_t)e * 384 + q] = roundtf(v);
}

// step 0: x=0, h=0 -> gates = biases only; identical for all nodes
__global__ void k_step0a()
{
    int j = threadIdx.x;
    int tg = j >> 5, jj = j & 31;
    int base = tg * 128 + jj;
    float gi = g_bias[base];
    float gf = g_bias[base + 32];
    float gg = g_bias[base + 64];
    float go = g_bias[base + 96];
    float c1 = sigm(gi) * tanhf(gg);          // c0 = 0
    float h1 = sigm(go) * tanhf(c1);
    g_c1[j] = c1;
    g_h1[j] = roundtf(h1);
}
__global__ void k_step0b()
{
    int i = blockIdx.x * blockDim.x + threadIdx.x;
    if (i >= O_NODES * HH) return;
    g_cs[i]  = g_c1[i & 511];
    g_hsB[i] = g_h1[i & 511];
}

// ghh1[p] = sum_k h1[k] * Whh_perm[p][k]
__global__ void k_ghh1()
{
    int p = blockIdx.x * blockDim.x + threadIdx.x;
    if (p >= 2048) return;
    const float* w = g_whx + (size_t)p * 1024;
    float s = 0.f;
    for (int k = 0; k < 512; ++k) s = fmaf(g_h1[k], w[k], s);
    g_ghh1[p] = s;
}

// pooled half of pc: pc[n][0..127 f4] = hbuf[lengths[n]&1][pos[n]]
__global__ void k_build_pc_h(const int* __restrict__ lengths)
{
    int i = blockIdx.x * blockDim.x + threadIdx.x;
    if (i >= O_NODES * 128) return;
    int n = i >> 7, q = i & 127;
    const float* hb = (lengths[n] & 1) ? g_hsB : g_hsA;
    ((float4*)g_pc)[(size_t)n * 256 + q] =
        ((const float4*)hb)[(size_t)g_pos[n] * 128 + q];
}

// ---------------- launcher -----------------------------------------------------
extern "C" void kernel_launch(void* const* d_in, const int* in_sizes, int n_in,
                              void* d_out, int out_size)
{
    const float* obj    = (const float*)d_in[0];
    const float* pred   = (const float*)d_in[1];
    const int*   edges  = (const int*)  d_in[2];
    const int*   nbr    = (const int*)  d_in[3];
    const int*   lengths= (const int*)  d_in[4];
    const float* W1     = (const float*)d_in[5];
    const float* b1     = (const float*)d_in[6];
    const float* W2     = (const float*)d_in[7];
    const float* b2     = (const float*)d_in[8];
    const float* Wih    = (const float*)d_in[9];
    const float* Whh    = (const float*)d_in[10];
    const float* bih    = (const float*)d_in[11];
    const float* bhh    = (const float*)d_in[12];
    const float* Wproj  = (const float*)d_in[13];
    const float* bproj  = (const float*)d_in[14];
    const float* Wout   = (const float*)d_in[15];
    const float* bout   = (const float*)d_in[16];
    float* out = (float*)d_out;

    const int L = in_sizes[3] / O_NODES;

    float *p_cur, *p_mid, *p_x32, *p_hsA, *p_hsB, *p_pc, *p_obj32;
    float *p_w1, *p_w2, *p_wproj, *p_wout;
    int *p_cnt;
    cudaGetSymbolAddress((void**)&p_cur,   g_cur);
    cudaGetSymbolAddress((void**)&p_mid,   g_mid);
    cudaGetSymbolAddress((void**)&p_x32,   g_x32);
    cudaGetSymbolAddress((void**)&p_hsA,   g_hsA);
    cudaGetSymbolAddress((void**)&p_hsB,   g_hsB);
    cudaGetSymbolAddress((void**)&p_pc,    g_pc);
    cudaGetSymbolAddress((void**)&p_obj32, g_obj32);
    cudaGetSymbolAddress((void**)&p_w1,    g_w1r);
    cudaGetSymbolAddress((void**)&p_w2,    g_w2r);
    cudaGetSymbolAddress((void**)&p_wproj, g_wprojr);
    cudaGetSymbolAddress((void**)&p_wout,  g_woutr);
    cudaGetSymbolAddress((void**)&p_cnt,   g_cnt);

    cudaFuncSetAttribute(tgemm<0, true >, cudaFuncAttributeMaxDynamicSharedMemorySize, TG_SMEM);
    cudaFuncSetAttribute(tgemm<1, true >, cudaFuncAttributeMaxDynamicSharedMemorySize, TG_SMEM);
    cudaFuncSetAttribute(tgemm<2, true >, cudaFuncAttributeMaxDynamicSharedMemorySize, TG_SMEM);
    cudaFuncSetAttribute(tgemm<3, true >, cudaFuncAttributeMaxDynamicSharedMemorySize, TG_SMEM);
    cudaFuncSetAttribute(lstm_step<true >, cudaFuncAttributeMaxDynamicSharedMemorySize, TG_SMEM);
    cudaFuncSetAttribute(lstm_step<false>, cudaFuncAttributeMaxDynamicSharedMemorySize, TG_SMEM);

    const int MT_E = (T_EDGES + 127) / 128;        // 391
    const int MT_O = (O_NODES + 127) / 128;        // 79

    // prep (weight rounding/permutation + obj round + bias + hist zero)
    k_prep<<<(PRE_TOTAL + 255) / 256, 256>>>(W1, W2, Wih, Whh, Wproj, Wout, obj, bih, bhh);

    // node sort by length (descending)
    k_hist<<<(O_NODES + 255) / 256, 256>>>(lengths);
    k_scan<<<1, 1>>>(L);
    k_scatter<<<(O_NODES + 255) / 256, 256>>>(lengths);

    // edge MLP; GEMM2 writes new_s/new_o (rounded) to g_x32 and new_p to out
    k_build_cur<<<(T_EDGES * 384 + 255) / 256, 256>>>(obj, pred, edges);
    tgemm<1, true ><<<dim3(4, MT_E), 128, TG_SMEM>>>(p_cur, 384, p_w1, 384, b1,
        p_mid, 512, nullptr, T_EDGES);
    tgemm<2, true ><<<dim3(9, MT_E), 128, TG_SMEM>>>(p_mid, 512, p_w2, 512, b2,
        out + (size_t)O_NODES * 128, 128, p_x32, T_EDGES);

    // prev = obj @ Wproj^T + bproj, written directly into pc cols [512,1024)
    tgemm<3, true ><<<dim3(4, MT_O), 128, TG_SMEM>>>(p_obj32, 128, p_wproj, 128, bproj,
        p_pc + 512, 1024, nullptr, O_NODES);

    // LSTM: step 0 closed form (buffer B); step 1 = x-only GEMM + ghh1 broadcast
    // (buffer A); steps t=2..L-1 fused [h|x] GEMM + pointwise, ping-pong.
    k_step0a<<<1, 512>>>();
    k_step0b<<<(O_NODES * HH + 255) / 256, 256>>>();
    k_ghh1<<<8, 256>>>();
    lstm_step<true ><<<dim3(16, MT_O), 128, TG_SMEM>>>(p_hsB, 1, L, nbr, p_cnt + 1, p_hsA);
    for (int t = 2; t < L; ++t) {
        float* hin  = (t & 1) ? p_hsB : p_hsA;
        float* hout = (t & 1) ? p_hsA : p_hsB;
        lstm_step<false><<<dim3(16, MT_O), 128, TG_SMEM>>>(hin, t, L, nbr, p_cnt + t, hout);
    }

    // pooled half of pc, then new_obj = pc @ Wout^T + bout (exact epilogue)
    k_build_pc_h<<<(O_NODES * 128 + 255) / 256, 256>>>(lengths);
    tgemm<0, true ><<<dim3(1, MT_O), 128, TG_SMEM>>>(p_pc, 1024, p_wout, 1024, bout,
        out, 128, nullptr, O_NODES);
}

// round 17
// speedup vs baseline: 1.0267x; 1.0255x over previous
#include <cuda_runtime.h>
#include <cstdint>
#include <math.h>

// Problem constants
#define O_NODES 10000
#define T_EDGES 50000
#define HH      512
#define NG      2048
#define HIST_SZ 131072

// ---------------- scratch (__device__ globals) --------------------------------
__device__ float g_predr[(size_t)T_EDGES * 128];       // tf32-rounded pred
__device__ float g_mid [(size_t)T_EDGES * HH];
__device__ float g_x32 [(size_t)(2 * T_EDGES) * HH];   // [new_s rows | new_o rows]
__device__ float g_hsA [(size_t)O_NODES * HH];         // h ping-pong buffer 0
__device__ float g_hsB [(size_t)O_NODES * HH];         // h ping-pong buffer 1
__device__ float g_cs  [(size_t)O_NODES * HH];         // full fp32 c state
__device__ float g_pc  [(size_t)O_NODES * 1024];       // [pooled | prev]
__device__ float g_obj32[(size_t)O_NODES * 128];
// tf32-rounded weights
__device__ float g_w1r   [512  * 384];
__device__ float g_w2r   [1152 * 512];
__device__ float g_whx   [2048 * 1024];           // [Whh_perm | Wih_perm] rows
__device__ float g_wprojr[512  * 128];
__device__ float g_woutr [128  * 1024];
__device__ float g_bias  [2048];                  // permuted bih+bhh
__device__ float g_h1[512];
__device__ float g_c1[512];
__device__ float g_ghh1[2048];                    // h1 @ Whh^T (permuted cols)
// sort scratch
__device__ int g_hist[HIST_SZ];
__device__ int g_cursor[HIST_SZ];
__device__ int g_cnt[HIST_SZ];
__device__ int g_order[O_NODES];
__device__ int g_pos[O_NODES];

// ---------------- helpers ------------------------------------------------------
__device__ __forceinline__ float roundtf(float x) {
    unsigned u;
    asm("cvt.rna.tf32.f32 %0, %1;" : "=r"(u) : "f"(x));
    return __uint_as_float(u);
}
__device__ __forceinline__ float sigm(float x) { return 1.f / (1.f + expf(-x)); }

__device__ __forceinline__ void mma_tf32(float* d, const unsigned* a, const unsigned* b) {
    asm volatile(
        "mma.sync.aligned.m16n8k8.row.col.f32.tf32.tf32.f32 "
        "{%0,%1,%2,%3}, {%4,%5,%6,%7}, {%8,%9}, {%0,%1,%2,%3};\n"
        : "+f"(d[0]), "+f"(d[1]), "+f"(d[2]), "+f"(d[3])
        : "r"(a[0]), "r"(a[1]), "r"(a[2]), "r"(a[3]), "r"(b[0]), "r"(b[1]));
}
__device__ __forceinline__ void cpa16(unsigned sdst, const float* gsrc, int src_bytes) {
    asm volatile("cp.async.cg.shared.global [%0], [%1], 16, %2;\n"
                 :: "r"(sdst), "l"(gsrc), "r"(src_bytes) : "memory");
}
__device__ __forceinline__ void cpa_commit() {
    asm volatile("cp.async.commit_group;\n" ::: "memory");
}
template<int N>
__device__ __forceinline__ void cpa_wait() {
    asm volatile("cp.async.wait_group %0;\n" :: "n"(N) : "memory");
}

#define PITCH   36
#define ASTG    (128 * PITCH)          // floats per A stage
#define TG_SMEM (4 * ASTG * 4)         // bytes: 2 stages x (A+B)

// ---------------- tf32 tensor-core GEMM ----------------------------------------
// C[M,N] = epi(A[M,K] @ B[N,K]^T). Inputs pre-rounded to tf32.
// Block 128x128, 4 warps x (64x64), BK=32 per stage, 2-stage cp.async.
// EPI: 0 exact(+bias) | 1 edge-MLP1: A gathered as [obj32[s]|predr[e]|obj32[o]],
//      relu+round(+bias) | 2 newt-split: relu; cols<512 -> round->X rows;
//      [512,640) -> fp32 C (new_p); >=640 -> round->X rows+T_EDGES | 3 round(+bias)
template<int EPI, bool BIAS>
__global__ void __launch_bounds__(128, 2)
tgemm(const float* __restrict__ A, int lda,
      const float* __restrict__ B, int K,
      const float* __restrict__ bias,
      float* __restrict__ C, int ldc,
      float* __restrict__ X, int M,
      const int* __restrict__ edges)
{
    const int m0 = blockIdx.y * 128;
    if (m0 >= M) return;
    const int n0 = blockIdx.x * 128;

    extern __shared__ float smem[];
    __shared__ int s_s[128], s_o[128];
    const unsigned sbase = (unsigned)__cvta_generic_to_shared(smem);

    const int tid  = threadIdx.x;
    const int warp = tid >> 5, lane = tid & 31;
    const int r = lane >> 2, c = lane & 3;
    const int wm = (warp & 1) * 64;
    const int wn = (warp >> 1) * 64;

    if (EPI == 1) {
        int row = m0 + tid;
        int s = 0, o = 0;
        if (row < M) { s = edges[2 * row]; o = edges[2 * row + 1]; }
        s_s[tid] = s;
        s_o[tid] = o;
        __syncthreads();
    }

    float acc[4][8][4];
#pragma unroll
    for (int i = 0; i < 4; i++)
#pragma unroll
        for (int j = 0; j < 8; j++)
#pragma unroll
            for (int q = 0; q < 4; q++) acc[i][j][q] = 0.f;

    const int nk = K >> 5;

    auto load_stage = [&](int it, int stg) {
        int k0 = it << 5;
#pragma unroll
        for (int i = 0; i < 8; i++) {
            int q = tid + i * 128;
            int row = q >> 3, f4 = q & 7;
            unsigned soff = (unsigned)((stg * ASTG + row * PITCH + f4 * 4) * 4);
            const float* ga;
            if (EPI == 1) {
                if (k0 < 128)       ga = g_obj32 + (size_t)s_s[row] * 128 + k0 + f4 * 4;
                else if (k0 < 256)  ga = g_predr + (size_t)(m0 + row) * 128 + (k0 - 128) + f4 * 4;
                else                ga = g_obj32 + (size_t)s_o[row] * 128 + (k0 - 256) + f4 * 4;
            } else {
                ga = A + (size_t)(m0 + row) * lda + k0 + f4 * 4;
            }
            cpa16(sbase + soff, ga, ((m0 + row) < M) ? 16 : 0);
            const float* gb = B + (size_t)(n0 + row) * K + k0 + f4 * 4;
            cpa16(sbase + (unsigned)(2 * ASTG * 4) + soff, gb, 16);
        }
        cpa_commit();
    };

    load_stage(0, 0);

    for (int it = 0; it < nk; ++it) {
        if (it + 1 < nk) { load_stage(it + 1, (it + 1) & 1); cpa_wait<1>(); }
        else             { cpa_wait<0>(); }
        __syncthreads();

        const float* As = smem + (it & 1) * ASTG;
        const float* Bs = smem + 2 * ASTG + (it & 1) * ASTG;
#pragma unroll
        for (int kk = 0; kk < 32; kk += 8) {
            unsigned ua[4][4], ub[8][2];
#pragma unroll
            for (int mt = 0; mt < 4; mt++) {
                int mb = wm + mt * 16 + r;
                ua[mt][0] = __float_as_uint(As[(mb    ) * PITCH + kk + c    ]);
                ua[mt][1] = __float_as_uint(As[(mb + 8) * PITCH + kk + c    ]);
                ua[mt][2] = __float_as_uint(As[(mb    ) * PITCH + kk + c + 4]);
                ua[mt][3] = __float_as_uint(As[(mb + 8) * PITCH + kk + c + 4]);
            }
#pragma unroll
            for (int nf = 0; nf < 8; nf++) {
                int nb = wn + nf * 8 + r;
                ub[nf][0] = __float_as_uint(Bs[nb * PITCH + kk + c    ]);
                ub[nf][1] = __float_as_uint(Bs[nb * PITCH + kk + c + 4]);
            }
#pragma unroll
            for (int mt = 0; mt < 4; mt++)
#pragma unroll
                for (int nf = 0; nf < 8; nf++)
                    mma_tf32(acc[mt][nf], ua[mt], ub[nf]);
        }
        __syncthreads();
    }

    const int cc2 = c * 2;
#pragma unroll
    for (int mt = 0; mt < 4; mt++) {
        int row0 = m0 + wm + mt * 16 + r;
#pragma unroll
        for (int nf = 0; nf < 8; nf++) {
            int col = n0 + wn + nf * 8 + cc2;
            float bx = 0.f, by = 0.f;
            if (BIAS) { bx = bias[col]; by = bias[col + 1]; }
#pragma unroll
            for (int h = 0; h < 2; h++) {
                int row = row0 + h * 8;
                if (row >= M) continue;
                float vx = acc[mt][nf][h * 2 + 0] + bx;
                float vy = acc[mt][nf][h * 2 + 1] + by;
                if (EPI == 1 || EPI == 2) { vx = fmaxf(vx, 0.f); vy = fmaxf(vy, 0.f); }
                if (EPI == 1 || EPI == 3) { vx = roundtf(vx); vy = roundtf(vy); }
                if (EPI == 2) {
                    if (col < 512) {
                        *(float2*)(X + (size_t)row * HH + col) =
                            make_float2(roundtf(vx), roundtf(vy));
                    } else if (col < 640) {
                        *(float2*)(C + (size_t)row * 128 + (col - 512)) =
                            make_float2(vx, vy);
                    } else {
                        *(float2*)(X + (size_t)(row + T_EDGES) * HH + (col - 640)) =
                            make_float2(roundtf(vx), roundtf(vy));
                    }
                } else {
                    *(float2*)(C + (size_t)row * ldc + col) = make_float2(vx, vy);
                }
            }
        }
    }
}

// ---------------- fused LSTM step: gates = [h|x_gathered] @ [Whh|Wih]^T --------
// T1: step 1 — x-only GEMM (K=512, B=Wih half), ghh1 broadcast added in epilogue.
// else: K=1024; stages <512 read h from hin, >=512 read x row sidx[row].
template<bool T1>
__global__ void __launch_bounds__(128, 2)
lstm_step(const float* __restrict__ hin,
          int t, int L, const int* __restrict__ nbr,
          const int* __restrict__ mdev,
          float* __restrict__ hout)
{
    const int M = *mdev;
    const int m0 = blockIdx.y * 128;
    if (m0 >= M) return;
    const int n0 = blockIdx.x * 128;

    extern __shared__ float smem[];
    __shared__ int sidx[128];
    const unsigned sbase = (unsigned)__cvta_generic_to_shared(smem);

    const int tid  = threadIdx.x;
    const int warp = tid >> 5, lane = tid & 31;
    const int r = lane >> 2, c = lane & 3;
    const int wm = (warp & 1) * 64;
    const int wn = (warp >> 1) * 64;

    {
        int row = m0 + tid;
        int s = 0;
        if (row < M) s = nbr[(size_t)g_order[row] * L + t] - 1;  // active => >0
        sidx[tid] = s;
    }
    __syncthreads();

    const float* Bw = T1 ? (g_whx + 512) : g_whx;
    const int K = T1 ? 512 : 1024;
    const int nk = K >> 5;

    float acc[4][8][4];
#pragma unroll
    for (int i = 0; i < 4; i++)
#pragma unroll
        for (int j = 0; j < 8; j++)
#pragma unroll
            for (int q = 0; q < 4; q++) acc[i][j][q] = 0.f;

    auto load_stage = [&](int it, int stg) {
        int k0 = it << 5;
#pragma unroll
        for (int i = 0; i < 8; i++) {
            int q = tid + i * 128;
            int row = q >> 3, f4 = q & 7;
            unsigned soff = (unsigned)((stg * ASTG + row * PITCH + f4 * 4) * 4);
            const float* ga;
            if (T1)            ga = g_x32 + (size_t)sidx[row] * HH + k0 + f4 * 4;
            else if (k0 < 512) ga = hin + (size_t)(m0 + row) * HH + k0 + f4 * 4;
            else               ga = g_x32 + (size_t)sidx[row] * HH + (k0 - 512) + f4 * 4;
            cpa16(sbase + soff, ga, ((m0 + row) < M) ? 16 : 0);
            const float* gb = Bw + (size_t)(n0 + row) * 1024 + k0 + f4 * 4;
            cpa16(sbase + (unsigned)(2 * ASTG * 4) + soff, gb, 16);
        }
        cpa_commit();
    };

    load_stage(0, 0);

    for (int it = 0; it < nk; ++it) {
        if (it + 1 < nk) { load_stage(it + 1, (it + 1) & 1); cpa_wait<1>(); }
        else             { cpa_wait<0>(); }
        __syncthreads();

        const float* As = smem + (it & 1) * ASTG;
        const float* Bs = smem + 2 * ASTG + (it & 1) * ASTG;
#pragma unroll
        for (int kk = 0; kk < 32; kk += 8) {
            unsigned ua[4][4], ub[8][2];
#pragma unroll
            for (int mt = 0; mt < 4; mt++) {
                int mb = wm + mt * 16 + r;
                ua[mt][0] = __float_as_uint(As[(mb    ) * PITCH + kk + c    ]);
                ua[mt][1] = __float_as_uint(As[(mb + 8) * PITCH + kk + c    ]);
                ua[mt][2] = __float_as_uint(As[(mb    ) * PITCH + kk + c + 4]);
                ua[mt][3] = __float_as_uint(As[(mb + 8) * PITCH + kk + c + 4]);
            }
#pragma unroll
            for (int nf = 0; nf < 8; nf++) {
                int nb = wn + nf * 8 + r;
                ub[nf][0] = __float_as_uint(Bs[nb * PITCH + kk + c    ]);
                ub[nf][1] = __float_as_uint(Bs[nb * PITCH + kk + c + 4]);
            }
#pragma unroll
            for (int mt = 0; mt < 4; mt++)
#pragma unroll
                for (int nf = 0; nf < 8; nf++)
                    mma_tf32(acc[mt][nf], ua[mt], ub[nf]);
        }
        __syncthreads();
    }

    // stage 128x128 gate tile in smem, then pointwise
    float* gbuf = smem;   // 128 x 132 floats = 67584 <= 73728
    const int cc2 = c * 2;
#pragma unroll
    for (int mt = 0; mt < 4; mt++) {
        int lr0 = wm + mt * 16 + r;
#pragma unroll
        for (int nf = 0; nf < 8; nf++) {
            int col = wn + nf * 8 + cc2;
            gbuf[lr0 * 132 + col]           = acc[mt][nf][0];
            gbuf[lr0 * 132 + col + 1]       = acc[mt][nf][1];
            gbuf[(lr0 + 8) * 132 + col]     = acc[mt][nf][2];
            gbuf[(lr0 + 8) * 132 + col + 1] = acc[mt][nf][3];
        }
    }
    __syncthreads();
    const int jj0 = (tid & 3) * 8;
#pragma unroll
    for (int pass = 0; pass < 4; pass++) {
        int rl = pass * 32 + (tid >> 2);
        int row = m0 + rl;
        if (row < M) {
#pragma unroll
            for (int u = 0; u < 8; u++) {
                int jj = jj0 + u;
                float gi = gbuf[rl * 132 + jj]      + g_bias[n0 + jj];
                float gf = gbuf[rl * 132 + 32 + jj] + g_bias[n0 + 32 + jj];
                float gg = gbuf[rl * 132 + 64 + jj] + g_bias[n0 + 64 + jj];
                float go = gbuf[rl * 132 + 96 + jj] + g_bias[n0 + 96 + jj];
                if (T1) {
                    gi += g_ghh1[n0 + jj];
                    gf += g_ghh1[n0 + 32 + jj];
                    gg += g_ghh1[n0 + 64 + jj];
                    go += g_ghh1[n0 + 96 + jj];
                }
                int j = (n0 >> 2) + jj;    // global hidden index
                float cc = g_cs[(size_t)row * HH + j];
                float c2 = sigm(gf) * cc + sigm(gi) * tanhf(gg);
                float h2 = sigm(go) * tanhf(c2);
                g_cs[(size_t)row * HH + j] = c2;
                hout[(size_t)row * HH + j] = roundtf(h2);
            }
        }
    }
}

// ---------------- prep / pointwise kernels -------------------------------------
#define PRE_W1    0
#define PRE_W2    (PRE_W1 + 512 * 384)
#define PRE_WIH   (PRE_W2 + 1152 * 512)
#define PRE_WHH   (PRE_WIH + 2048 * 512)
#define PRE_WPROJ (PRE_WHH + 2048 * 512)
#define PRE_WOUT  (PRE_WPROJ + 512 * 128)
#define PRE_OBJ   (PRE_WOUT + 128 * 1024)
#define PRE_PRED  (PRE_OBJ + O_NODES * 128)
#define PRE_BIAS  (PRE_PRED + T_EDGES * 128)
#define PRE_HIST  (PRE_BIAS + 2048)
#define PRE_TOTAL (PRE_HIST + HIST_SZ)

__global__ void k_prep(const float* __restrict__ W1, const float* __restrict__ W2,
                       const float* __restrict__ Wih, const float* __restrict__ Whh,
                       const float* __restrict__ Wproj, const float* __restrict__ Wout,
                       const float* __restrict__ obj, const float* __restrict__ pred,
                       const float* __restrict__ bih, const float* __restrict__ bhh)
{
    int i = blockIdx.x * blockDim.x + threadIdx.x;
    if (i >= PRE_TOTAL) return;
    if (i < PRE_W2) {
        g_w1r[i] = roundtf(W1[i]);
    } else if (i < PRE_WIH) {
        int q = i - PRE_W2;  g_w2r[q] = roundtf(W2[q]);
    } else if (i < PRE_WPROJ) {
        int q = (i < PRE_WHH) ? (i - PRE_WIH) : (i - PRE_WHH);
        const float* W = (i < PRE_WHH) ? Wih : Whh;
        int half = (i < PRE_WHH) ? 512 : 0;    // Wih -> cols [512,1024), Whh -> [0,512)
        int p = q >> 9, k = q & 511;
        int g = (p >> 5) & 3, tg = p >> 7, jj = p & 31;
        int orig = g * 512 + tg * 32 + jj;
        g_whx[(size_t)p * 1024 + half + k] = roundtf(W[(size_t)orig * 512 + k]);
    } else if (i < PRE_WOUT) {
        int q = i - PRE_WPROJ;  g_wprojr[q] = roundtf(Wproj[q]);
    } else if (i < PRE_OBJ) {
        int q = i - PRE_WOUT;  g_woutr[q] = roundtf(Wout[q]);
    } else if (i < PRE_PRED) {
        int q = i - PRE_OBJ;  g_obj32[q] = roundtf(obj[q]);
    } else if (i < PRE_BIAS) {
        int q = i - PRE_PRED;  g_predr[q] = roundtf(pred[q]);
    } else if (i < PRE_HIST) {
        int p = i - PRE_BIAS;
        int g = (p >> 5) & 3, tg = p >> 7, jj = p & 31;
        int orig = g * 512 + tg * 32 + jj;
        g_bias[p] = bih[orig] + bhh[orig];
    } else {
        g_hist[i - PRE_HIST] = 0;
    }
}

__global__ void k_hist(const int* __restrict__ lengths)
{
    int n = blockIdx.x * blockDim.x + threadIdx.x;
    if (n < O_NODES) atomicAdd(&g_hist[lengths[n]], 1);
}
__global__ void k_scan(int L)
{
    int run = 0;
    for (int len = L; len >= 0; --len) {
        g_cursor[len] = run;
        g_cnt[len]    = run;
        run += g_hist[len];
    }
}
__global__ void k_scatter(const int* __restrict__ lengths)
{
    int n = blockIdx.x * blockDim.x + threadIdx.x;
    if (n >= O_NODES) return;
    int pos = atomicAdd(&g_cursor[lengths[n]], 1);
    g_order[pos] = n;
    g_pos[n] = pos;
}

// step 0: x=0, h=0 -> gates = biases only; identical for all nodes
__global__ void k_step0a()
{
    int j = threadIdx.x;
    int tg = j >> 5, jj = j & 31;
    int base = tg * 128 + jj;
    float gi = g_bias[base];
    float gf = g_bias[base + 32];
    float gg = g_bias[base + 64];
    float go = g_bias[base + 96];
    float c1 = sigm(gi) * tanhf(gg);          // c0 = 0
    float h1 = sigm(go) * tanhf(c1);
    g_c1[j] = c1;
    g_h1[j] = roundtf(h1);
}
__global__ void k_step0b()
{
    int i = blockIdx.x * blockDim.x + threadIdx.x;
    if (i >= O_NODES * HH) return;
    g_cs[i]  = g_c1[i & 511];
    g_hsB[i] = g_h1[i & 511];
}

// ghh1[p] = sum_k h1[k] * Whh_perm[p][k]
__global__ void k_ghh1()
{
    int p = blockIdx.x * blockDim.x + threadIdx.x;
    if (p >= 2048) return;
    const float* w = g_whx + (size_t)p * 1024;
    float s = 0.f;
    for (int k = 0; k < 512; ++k) s = fmaf(g_h1[k], w[k], s);
    g_ghh1[p] = s;
}

// pooled half of pc: pc[n][0..127 f4] = hbuf[lengths[n]&1][pos[n]]
__global__ void k_build_pc_h(const int* __restrict__ lengths)
{
    int i = blockIdx.x * blockDim.x + threadIdx.x;
    if (i >= O_NODES * 128) return;
    int n = i >> 7, q = i & 127;
    const float* hb = (lengths[n] & 1) ? g_hsB : g_hsA;
    ((float4*)g_pc)[(size_t)n * 256 + q] =
        ((const float4*)hb)[(size_t)g_pos[n] * 128 + q];
}

// ---------------- launcher -----------------------------------------------------
extern "C" void kernel_launch(void* const* d_in, const int* in_sizes, int n_in,
                              void* d_out, int out_size)
{
    const float* obj    = (const float*)d_in[0];
    const float* pred   = (const float*)d_in[1];
    const int*   edges  = (const int*)  d_in[2];
    const int*   nbr    = (const int*)  d_in[3];
    const int*   lengths= (const int*)  d_in[4];
    const float* W1     = (const float*)d_in[5];
    const float* b1     = (const float*)d_in[6];
    const float* W2     = (const float*)d_in[7];
    const float* b2     = (const float*)d_in[8];
    const float* Wih    = (const float*)d_in[9];
    const float* Whh    = (const float*)d_in[10];
    const float* bih    = (const float*)d_in[11];
    const float* bhh    = (const float*)d_in[12];
    const float* Wproj  = (const float*)d_in[13];
    const float* bproj  = (const float*)d_in[14];
    const float* Wout   = (const float*)d_in[15];
    const float* bout   = (const float*)d_in[16];
    float* out = (float*)d_out;

    const int L = in_sizes[3] / O_NODES;

    float *p_mid, *p_x32, *p_hsA, *p_hsB, *p_pc, *p_obj32;
    float *p_w1, *p_w2, *p_wproj, *p_wout;
    int *p_cnt;
    cudaGetSymbolAddress((void**)&p_mid,   g_mid);
    cudaGetSymbolAddress((void**)&p_x32,   g_x32);
    cudaGetSymbolAddress((void**)&p_hsA,   g_hsA);
    cudaGetSymbolAddress((void**)&p_hsB,   g_hsB);
    cudaGetSymbolAddress((void**)&p_pc,    g_pc);
    cudaGetSymbolAddress((void**)&p_obj32, g_obj32);
    cudaGetSymbolAddress((void**)&p_w1,    g_w1r);
    cudaGetSymbolAddress((void**)&p_w2,    g_w2r);
    cudaGetSymbolAddress((void**)&p_wproj, g_wprojr);
    cudaGetSymbolAddress((void**)&p_wout,  g_woutr);
    cudaGetSymbolAddress((void**)&p_cnt,   g_cnt);

    cudaFuncSetAttribute(tgemm<0, true >, cudaFuncAttributeMaxDynamicSharedMemorySize, TG_SMEM);
    cudaFuncSetAttribute(tgemm<1, true >, cudaFuncAttributeMaxDynamicSharedMemorySize, TG_SMEM);
    cudaFuncSetAttribute(tgemm<2, true >, cudaFuncAttributeMaxDynamicSharedMemorySize, TG_SMEM);
    cudaFuncSetAttribute(tgemm<3, true >, cudaFuncAttributeMaxDynamicSharedMemorySize, TG_SMEM);
    cudaFuncSetAttribute(lstm_step<true >, cudaFuncAttributeMaxDynamicSharedMemorySize, TG_SMEM);
    cudaFuncSetAttribute(lstm_step<false>, cudaFuncAttributeMaxDynamicSharedMemorySize, TG_SMEM);

    const int MT_E = (T_EDGES + 127) / 128;        // 391
    const int MT_O = (O_NODES + 127) / 128;        // 79

    // prep (weight rounding/permutation + obj/pred round + bias + hist zero)
    k_prep<<<(PRE_TOTAL + 255) / 256, 256>>>(W1, W2, Wih, Whh, Wproj, Wout, obj, pred, bih, bhh);

    // node sort by length (descending)
    k_hist<<<(O_NODES + 255) / 256, 256>>>(lengths);
    k_scan<<<1, 1>>>(L);
    k_scatter<<<(O_NODES + 255) / 256, 256>>>(lengths);

    // edge MLP; GEMM1 gathers A rows from edges; GEMM2 writes new_s/new_o
    // (rounded) to g_x32 and new_p to out
    tgemm<1, true ><<<dim3(4, MT_E), 128, TG_SMEM>>>(nullptr, 0, p_w1, 384, b1,
        p_mid, 512, nullptr, T_EDGES, edges);
    tgemm<2, true ><<<dim3(9, MT_E), 128, TG_SMEM>>>(p_mid, 512, p_w2, 512, b2,
        out + (size_t)O_NODES * 128, 128, p_x32, T_EDGES, nullptr);

    // prev = obj @ Wproj^T + bproj, written directly into pc cols [512,1024)
    tgemm<3, true ><<<dim3(4, MT_O), 128, TG_SMEM>>>(p_obj32, 128, p_wproj, 128, bproj,
        p_pc + 512, 1024, nullptr, O_NODES, nullptr);

    // LSTM: step 0 closed form (buffer B); step 1 = x-only GEMM + ghh1 broadcast
    // (buffer A); steps t=2..L-1 fused [h|x] GEMM + pointwise, ping-pong.
    k_step0a<<<1, 512>>>();
    k_step0b<<<(O_NODES * HH + 255) / 256, 256>>>();
    k_ghh1<<<8, 256>>>();
    lstm_step<true ><<<dim3(16, MT_O), 128, TG_SMEM>>>(p_hsB, 1, L, nbr, p_cnt + 1, p_hsA);
    for (int t = 2; t < L; ++t) {
        float* hin  = (t & 1) ? p_hsB : p_hsA;
        float* hout = (t & 1) ? p_hsA : p_hsB;
        lstm_step<false><<<dim3(16, MT_O), 128, TG_SMEM>>>(hin, t, L, nbr, p_cnt + t, hout);
    }

    // pooled half of pc, then new_obj = pc @ Wout^T + bout (exact epilogue)
    k_build_pc_h<<<(O_NODES * 128 + 255) / 256, 256>>>(lengths);
    tgemm<0, true ><<<dim3(1, MT_O), 128, TG_SMEM>>>(p_pc, 1024, p_wout, 1024, bout,
        out, 128, nullptr, O_NODES, nullptr);
}